// round 1
// baseline (speedup 1.0000x reference)
#include <cuda_runtime.h>

// Energy-distance loss:
//   a1 = sum_{i,j} |lat_i - z_j|   * 2/(N*M*D)
//   b1 = sum_{i,j} |lat_i - lat_j| * 1/(N*N*D)
//   c1 = sum_{i,j} |z_i - z_j|     * 1/(M*M*D)
//   out = a1 - b1 - c1
// Distances via |a|^2+|b|^2-2ab with clamp-at-0 and sqrt, matching reference.

#define NROWS 16384
#define MROWS 4096
#define DDIM  64

// global accumulators + precomputed row norms (latent rows, then z rows)
__device__ double g_acc[3];
__device__ float  g_norm[NROWS + MROWS];

// ---------------------------------------------------------------------------
// packed fp32x2 FMA (Blackwell): d = a*b + d elementwise on two packed floats
__device__ __forceinline__ void fma2(unsigned long long& acc,
                                     unsigned long long a,
                                     unsigned long long b) {
    asm("fma.rn.f32x2 %0, %1, %2, %0;" : "+l"(acc) : "l"(a), "l"(b));
}

__device__ __forceinline__ float2 unpack2(unsigned long long v) {
    float2 r;
    asm("mov.b64 {%0, %1}, %2;" : "=f"(r.x), "=f"(r.y) : "l"(v));
    return r;
}

// ---------------------------------------------------------------------------
// prep: zero accumulators, compute per-row squared norms (fp32, like reference)
__global__ void prep_kernel(const float* __restrict__ lat,
                            const float* __restrict__ z) {
    int r = blockIdx.x * blockDim.x + threadIdx.x;
    if (r < 3) g_acc[r] = 0.0;
    if (r >= NROWS + MROWS) return;
    const float4* src = (r < NROWS)
        ? (const float4*)(lat + (size_t)r * DDIM)
        : (const float4*)(z + (size_t)(r - NROWS) * DDIM);
    float s = 0.f;
#pragma unroll
    for (int q = 0; q < DDIM / 4; q++) {
        float4 v = src[q];
        s = fmaf(v.x, v.x, s);
        s = fmaf(v.y, v.y, s);
        s = fmaf(v.z, v.z, s);
        s = fmaf(v.w, v.w, s);
    }
    g_norm[r] = s;
}

// ---------------------------------------------------------------------------
// main tile kernel: 128 threads, tile = 128 (i-rows of A) x 64 (j-rows of B),
// K = 64 fully resident. Each thread owns an 8x8 micro-tile, dot products
// accumulated packed over k (even/odd) in f32x2.
//
// SELF: A==B; only strict-upper pairs (j > i) are counted (doubled at
// finalize). Blocks are scheduled only where bj >= 2*bi.
template <bool SELF>
__global__ __launch_bounds__(128, 2)
void pair_kernel(const float* __restrict__ A, const float* __restrict__ B,
                 int nAoff, int nBoff, int TJ, int accIdx) {
    // swizzled shared tiles: float4 index f = k4 ^ ((row>>3)&7)
    __shared__ float4 sA4[128 * 16];
    __shared__ float4 sB4[64 * 16];

    int bi, bj;
    if (SELF) {
        int b = blockIdx.x;
        bi = 0;
        while (b >= TJ - 2 * bi) { b -= TJ - 2 * bi; bi++; }
        bj = 2 * bi + b;
    } else {
        bi = blockIdx.x / TJ;
        bj = blockIdx.x - bi * TJ;
    }
    const int i0 = bi * 128;
    const int j0 = bj * 64;
    const int tid = threadIdx.x;

    // ---- fill tiles (coalesced LDG.128, swizzled STS.128) ----
    {
        const float4* Ag = (const float4*)(A + (size_t)i0 * DDIM);
#pragma unroll
        for (int it = 0; it < 16; it++) {
            int lin = tid + it * 128;          // 0..2047
            int r = lin >> 4, k4 = lin & 15;
            sA4[r * 16 + (k4 ^ ((r >> 3) & 7))] = Ag[lin];
        }
        const float4* Bg = (const float4*)(B + (size_t)j0 * DDIM);
#pragma unroll
        for (int it = 0; it < 8; it++) {
            int lin = tid + it * 128;          // 0..1023
            int r = lin >> 4, k4 = lin & 15;
            sB4[r * 16 + (k4 ^ ((r >> 3) & 7))] = Bg[lin];
        }
    }
    __syncthreads();

    const int ty = tid >> 3;   // 0..15 -> i-group (8 rows)
    const int tx = tid & 7;    // 0..7  -> j-group (8 rows)
    const int cA = ty & 7;     // swizzle constant for A rows (row>>3 == ty)
    const int cB = tx & 7;     // swizzle constant for B rows (row>>3 == tx)

    const ulonglong2* a2 = (const ulonglong2*)sA4;
    const ulonglong2* b2 = (const ulonglong2*)sB4;

    int aRow[8], bRow[8];
#pragma unroll
    for (int u = 0; u < 8; u++) aRow[u] = (ty * 8 + u) * 16;
#pragma unroll
    for (int v = 0; v < 8; v++) bRow[v] = (tx * 8 + v) * 16;

    unsigned long long acc[8][8];
#pragma unroll
    for (int u = 0; u < 8; u++)
#pragma unroll
        for (int v = 0; v < 8; v++) acc[u][v] = 0ull;

    // ---- main loop: 16 float4-steps over k; each step = 4 k values ----
#pragma unroll 2
    for (int k4 = 0; k4 < 16; k4++) {
        const int fA = k4 ^ cA;
        const int fB = k4 ^ cB;
        ulonglong2 av[8], bv[8];
#pragma unroll
        for (int u = 0; u < 8; u++) av[u] = a2[aRow[u] + fA];
#pragma unroll
        for (int v = 0; v < 8; v++) bv[v] = b2[bRow[v] + fB];
#pragma unroll
        for (int u = 0; u < 8; u++) {
#pragma unroll
            for (int v = 0; v < 8; v++) {
                fma2(acc[u][v], av[u].x, bv[v].x);
                fma2(acc[u][v], av[u].y, bv[v].y);
            }
        }
    }

    // ---- epilogue: sq -> clamp -> sqrt -> masked sum ----
    float na[8], nb[8];
#pragma unroll
    for (int u = 0; u < 8; u++) na[u] = g_norm[nAoff + i0 + ty * 8 + u];
#pragma unroll
    for (int v = 0; v < 8; v++) nb[v] = g_norm[nBoff + j0 + tx * 8 + v];

    const int dji = SELF ? (j0 + tx * 8) - (i0 + ty * 8) : 0;

    float tsum = 0.f;
#pragma unroll
    for (int u = 0; u < 8; u++) {
        float rs = 0.f;
#pragma unroll
        for (int v = 0; v < 8; v++) {
            float2 p = unpack2(acc[u][v]);
            float dot = p.x + p.y;
            float sq = fmaf(-2.f, dot, na[u] + nb[v]);
            float dist = __fsqrt_rn(fmaxf(sq, 0.f));
            if (SELF) dist = (v + dji > u) ? dist : 0.f;  // keep j > i only
            rs += dist;
        }
        tsum += rs;
    }

    // warp reduce (fp32), then double atomic per warp
#pragma unroll
    for (int off = 16; off; off >>= 1)
        tsum += __shfl_xor_sync(0xffffffffu, tsum, off);
    if ((tid & 31) == 0) atomicAdd(&g_acc[accIdx], (double)tsum);
}

// ---------------------------------------------------------------------------
__global__ void finalize_kernel(float* out) {
    double a1 = g_acc[0] * (2.0 / ((double)NROWS * MROWS * DDIM));
    double b1 = g_acc[1] * (2.0 / ((double)NROWS * NROWS * DDIM));  // 2x: upper pairs only
    double c1 = g_acc[2] * (2.0 / ((double)MROWS * MROWS * DDIM));
    out[0] = (float)(a1 - b1 - c1);
}

// ---------------------------------------------------------------------------
extern "C" void kernel_launch(void* const* d_in, const int* in_sizes, int n_in,
                              void* d_out, int out_size) {
    const float* lat = (const float*)d_in[0];
    const float* z   = (const float*)d_in[1];
    // disambiguate by size in case of ordering surprises
    if (n_in >= 2 && in_sizes[0] == MROWS * DDIM && in_sizes[1] == NROWS * DDIM) {
        const float* t = lat; lat = z; z = t;
    }
    float* out = (float*)d_out;

    // norms + zero accumulators
    prep_kernel<<<(NROWS + MROWS + 255) / 256, 256>>>(lat, z);

    // cross: 128 i-tiles x 64 j-tiles
    pair_kernel<false><<<128 * 64, 128>>>(lat, z, 0, NROWS, 64, 0);

    // latent self: i-tiles 128(x128 rows), j-tiles 256(x64 rows), bj >= 2*bi
    // block count = sum_{bi=0}^{127} (256 - 2*bi) = 16512
    pair_kernel<true><<<16512, 128>>>(lat, lat, 0, 0, 256, 1);

    // z self: i-tiles 32, j-tiles 64, count = sum_{bi=0}^{31} (64 - 2*bi) = 1056
    pair_kernel<true><<<1056, 128>>>(z, z, NROWS, NROWS, 64, 2);

    finalize_kernel<<<1, 1>>>(out);
}

// round 4
// speedup vs baseline: 1.5218x; 1.5218x over previous
#include <cuda_runtime.h>
#include <cuda_bf16.h>
#include <cstdint>

// Energy-distance loss via bf16-split register GEMM (mma.sync m16n8k16).
//   dist(i,j) = sqrt(max(|a_i|^2 + |b_j|^2 - 2 a_i.b_j, 0))
//   dot = Ah.Bh + Ah.Bl + Al.Bh   (x = hi + lo bf16 split, fp32 accumulate)
// Norms in fp32 from original data; global sums in double via atomics.

#define NROWS 16384
#define MROWS 4096
#define DDIM  64

__device__ double g_acc[3];
__device__ float  g_norm[NROWS + MROWS];
__device__ __nv_bfloat16 g_lat_hi[NROWS * DDIM];
__device__ __nv_bfloat16 g_lat_lo[NROWS * DDIM];
__device__ __nv_bfloat16 g_z_hi[MROWS * DDIM];
__device__ __nv_bfloat16 g_z_lo[MROWS * DDIM];

// ---------------------------------------------------------------------------
__device__ __forceinline__ uint32_t smem_u32(const void* p) {
    uint32_t a;
    asm("{ .reg .u64 t; cvta.to.shared.u64 t, %1; cvt.u32.u64 %0, t; }"
        : "=r"(a) : "l"(p));
    return a;
}
// XOR-swizzle: rows are 128B; XOR (row & 7) into the 16B-chunk index.
__device__ __forceinline__ uint32_t swz_off(uint32_t off) {
    return off ^ ((off >> 3) & 0x70);
}
__device__ __forceinline__ void ldsm4(uint32_t* r, uint32_t addr) {
    asm volatile("ldmatrix.sync.aligned.m8n8.x4.shared.b16 {%0,%1,%2,%3}, [%4];"
                 : "=r"(r[0]), "=r"(r[1]), "=r"(r[2]), "=r"(r[3]) : "r"(addr));
}
__device__ __forceinline__ void mma16816(float* c, const uint32_t* a,
                                         uint32_t b0, uint32_t b1) {
    asm volatile(
        "mma.sync.aligned.m16n8k16.row.col.f32.bf16.bf16.f32 "
        "{%0,%1,%2,%3}, {%4,%5,%6,%7}, {%8,%9}, {%0,%1,%2,%3};"
        : "+f"(c[0]), "+f"(c[1]), "+f"(c[2]), "+f"(c[3])
        : "r"(a[0]), "r"(a[1]), "r"(a[2]), "r"(a[3]), "r"(b0), "r"(b1));
}

// ---------------------------------------------------------------------------
// prep: zero accumulators, bf16 hi/lo split, fp32 row norms
__global__ void prep_kernel(const float* __restrict__ lat,
                            const float* __restrict__ z) {
    int r = blockIdx.x * blockDim.x + threadIdx.x;
    if (r < 3) g_acc[r] = 0.0;
    if (r >= NROWS + MROWS) return;
    const float* src;
    __nv_bfloat16 *hi, *lo;
    if (r < NROWS) {
        src = lat + (size_t)r * DDIM;
        hi = g_lat_hi + (size_t)r * DDIM;
        lo = g_lat_lo + (size_t)r * DDIM;
    } else {
        int rr = r - NROWS;
        src = z + (size_t)rr * DDIM;
        hi = g_z_hi + (size_t)rr * DDIM;
        lo = g_z_lo + (size_t)rr * DDIM;
    }
    float s = 0.f;
#pragma unroll
    for (int q = 0; q < DDIM; q++) {
        float x = src[q];
        __nv_bfloat16 h = __float2bfloat16(x);
        hi[q] = h;
        lo[q] = __float2bfloat16(x - __bfloat162float(h));
        s = fmaf(x, x, s);
    }
    g_norm[r] = s;
}

// ---------------------------------------------------------------------------
// tile kernel: D[128 i, 64 j]; 4 warps, each computes 32 rows x 64 cols via
// mma.sync m16n8k16 over 3 bf16-split passes, then distance epilogue.
// SELF: A==B, only strict-upper pairs j>i counted (doubled in finalize);
// blocks scheduled only where bj >= 2*bi.
template <bool SELF>
__global__ __launch_bounds__(128, 4)
void pair_kernel(int nAoff, int nBoff, int TJ, int accIdx) {
    // 48KB static shared: tiles are K-contiguous bf16 rows of 128B, swizzled
    __shared__ uint4 sAh[1024], sAl[1024], sBh[512], sBl[512];

    const int tid = threadIdx.x, wid = tid >> 5, lane = tid & 31;

    int bi, bj;
    if (SELF) {
        int b = blockIdx.x;
        bi = 0;
        while (b >= TJ - 2 * bi) { b -= TJ - 2 * bi; bi++; }
        bj = 2 * bi + b;
    } else {
        bi = blockIdx.x / TJ;
        bj = blockIdx.x - bi * TJ;
    }
    const int i0 = bi * 128;
    const int j0 = bj * 64;

    const uint4 *Ah, *Al, *Bh, *Bl;
    if (accIdx == 0) {
        Ah = (const uint4*)g_lat_hi; Al = (const uint4*)g_lat_lo;
        Bh = (const uint4*)g_z_hi;   Bl = (const uint4*)g_z_lo;
    } else if (accIdx == 1) {
        Ah = (const uint4*)g_lat_hi; Al = (const uint4*)g_lat_lo;
        Bh = (const uint4*)g_lat_hi; Bl = (const uint4*)g_lat_lo;
    } else {
        Ah = (const uint4*)g_z_hi;   Al = (const uint4*)g_z_lo;
        Bh = (const uint4*)g_z_hi;   Bl = (const uint4*)g_z_lo;
    }

    // ---- fill tiles: coalesced LDG.128, swizzled STS.128 ----
#pragma unroll
    for (int it = 0; it < 8; it++) {
        int lin = tid + it * 128;                        // 0..1023
        uint32_t sw = swz_off((uint32_t)lin * 16) >> 4;  // uint4 index
        sAh[sw] = Ah[(size_t)i0 * 8 + lin];
        sAl[sw] = Al[(size_t)i0 * 8 + lin];
    }
#pragma unroll
    for (int it = 0; it < 4; it++) {
        int lin = tid + it * 128;                        // 0..511
        uint32_t sw = swz_off((uint32_t)lin * 16) >> 4;
        sBh[sw] = Bh[(size_t)j0 * 8 + lin];
        sBl[sw] = Bl[(size_t)j0 * 8 + lin];
    }
    __syncthreads();

    const uint32_t bAh = smem_u32(sAh), bAl = smem_u32(sAl);
    const uint32_t bBh = smem_u32(sBh), bBl = smem_u32(sBl);

    // ldmatrix source offsets (byte offsets before swizzle):
    // A (x4 over 16x16): row = w*32 + mt*16 + lane%16, kbyte = (lane/16)*16
    const uint32_t aRowByte = (uint32_t)(wid * 32 + (lane & 15)) * 128
                              + ((lane >> 4) << 4);
    // B (x4 over n16 x k16): nrow = p*16 + (lane&7) + ((lane>>4)<<3),
    //                        kbyte = ((lane>>3)&1)*16
    const uint32_t bRowByte = (uint32_t)((lane & 7) + ((lane >> 4) << 3)) * 128
                              + (((lane >> 3) & 1) << 4);

    float acc[2][8][4];
#pragma unroll
    for (int mt = 0; mt < 2; mt++)
#pragma unroll
        for (int nt = 0; nt < 8; nt++)
#pragma unroll
            for (int e = 0; e < 4; e++) acc[mt][nt][e] = 0.f;

    // ---- 3 split passes x 4 k-steps ----
#pragma unroll
    for (int sp = 0; sp < 3; sp++) {
        const uint32_t aBase = (sp < 2) ? bAh : bAl;
        const uint32_t bBase = (sp == 1) ? bBl : bBh;
#pragma unroll
        for (int k4 = 0; k4 < 4; k4++) {
            const uint32_t kb = (uint32_t)k4 * 32;
            uint32_t afrag[2][4];
#pragma unroll
            for (int mt = 0; mt < 2; mt++)
                ldsm4(afrag[mt],
                      aBase + swz_off(aRowByte + (uint32_t)mt * 16 * 128 + kb));
            uint32_t bfrag[4][4];
#pragma unroll
            for (int p = 0; p < 4; p++)
                ldsm4(bfrag[p],
                      bBase + swz_off(bRowByte + (uint32_t)p * 16 * 128 + kb));
#pragma unroll
            for (int mt = 0; mt < 2; mt++)
#pragma unroll
                for (int nt = 0; nt < 8; nt++)
                    mma16816(acc[mt][nt], afrag[mt],
                             bfrag[nt >> 1][(nt & 1) * 2],
                             bfrag[nt >> 1][(nt & 1) * 2 + 1]);
        }
    }

    // ---- epilogue: dist = sqrt(max(na + nb - 2*dot, 0)), masked sum ----
    float na4[4];
    {
        int r0 = nAoff + i0 + wid * 32 + (lane >> 2);
#pragma unroll
        for (int q = 0; q < 4; q++) na4[q] = g_norm[r0 + q * 8];
    }
    float nbv[16];
    {
        int c0 = nBoff + j0 + (lane & 3) * 2;
#pragma unroll
        for (int nt = 0; nt < 8; nt++) {
            nbv[nt * 2]     = g_norm[c0 + nt * 8];
            nbv[nt * 2 + 1] = g_norm[c0 + nt * 8 + 1];
        }
    }

    const int ibase = i0 + wid * 32 + (lane >> 2);
    const int jbase = j0 + (lane & 3) * 2;

    float s = 0.f;
#pragma unroll
    for (int mt = 0; mt < 2; mt++) {
#pragma unroll
        for (int nt = 0; nt < 8; nt++) {
#pragma unroll
            for (int e = 0; e < 4; e++) {
                float dot = acc[mt][nt][e];
                float sq = fmaf(-2.f, dot,
                                na4[mt * 2 + (e >> 1)] + nbv[nt * 2 + (e & 1)]);
                float dist = sqrtf(fmaxf(sq, 0.f));
                if (SELF) {
                    int ii = ibase + mt * 16 + (e >> 1) * 8;
                    int jj = jbase + nt * 8 + (e & 1);
                    if (jj <= ii) dist = 0.f;
                }
                s += dist;
            }
        }
    }
#pragma unroll
    for (int off = 16; off; off >>= 1)
        s += __shfl_xor_sync(0xffffffffu, s, off);
    if (lane == 0) atomicAdd(&g_acc[accIdx], (double)s);
}

// ---------------------------------------------------------------------------
__global__ void finalize_kernel(float* out) {
    double a1 = g_acc[0] * (2.0 / ((double)NROWS * MROWS * DDIM));
    double b1 = g_acc[1] * (2.0 / ((double)NROWS * NROWS * DDIM));  // 2x: upper only
    double c1 = g_acc[2] * (2.0 / ((double)MROWS * MROWS * DDIM));
    out[0] = (float)(a1 - b1 - c1);
}

// ---------------------------------------------------------------------------
extern "C" void kernel_launch(void* const* d_in, const int* in_sizes, int n_in,
                              void* d_out, int out_size) {
    const float* lat = (const float*)d_in[0];
    const float* z   = (const float*)d_in[1];
    if (n_in >= 2 && in_sizes[0] == MROWS * DDIM && in_sizes[1] == NROWS * DDIM) {
        const float* t = lat; lat = z; z = t;
    }
    float* out = (float*)d_out;

    prep_kernel<<<(NROWS + MROWS + 255) / 256, 256>>>(lat, z);

    // cross: 128 i-tiles x 64 j-tiles
    pair_kernel<false><<<128 * 64, 128>>>(0, NROWS, 64, 0);
    // latent self: TI=128, TJ=256, bj>=2*bi -> 16512 blocks
    pair_kernel<true><<<16512, 128>>>(0, 0, 256, 1);
    // z self: TI=32, TJ=64 -> 1056 blocks
    pair_kernel<true><<<1056, 128>>>(NROWS, NROWS, 64, 2);

    finalize_kernel<<<1, 1>>>(out);
}

// round 5
// speedup vs baseline: 2.8305x; 1.8600x over previous
#include <cuda_runtime.h>
#include <cstdint>

// Energy-distance loss via single-pass tf32 register GEMM (mma.m16n8k8).
//   dist(i,j) = sqrt(max(|a_i|^2 + |b_j|^2 - 2 a_i.b_j, 0))
// Inputs pre-rounded to tf32 (cvt.rna); norms fp32 from original data;
// global sums in double via one atomic per CTA.

#define NROWS 16384
#define MROWS 4096
#define DDIM  64

__device__ double   g_acc[3];
__device__ float    g_norm[NROWS + MROWS];
__device__ uint32_t g_lat_t[NROWS * DDIM];   // tf32-formatted bits
__device__ uint32_t g_z_t[MROWS * DDIM];

// smem layout in 32-bit words (dynamic):
//   A tile 128 x 64, row stride 68   -> [0, 8704)
//   B tile  64 x 64, row stride 68   -> [8704, 13056)
//   nb[64], na[128], red[8]
static constexpr int SM_B   = 8704;
static constexpr int SM_NB  = 13056;
static constexpr int SM_NA  = 13120;
static constexpr int SM_RED = 13248;
static constexpr int SM_WORDS = 13256;
static constexpr int SM_BYTES = SM_WORDS * 4;   // 53024

// ---------------------------------------------------------------------------
__device__ __forceinline__ void mma_tf32(float* c, const uint32_t* a,
                                         uint32_t b0, uint32_t b1) {
    asm volatile(
        "mma.sync.aligned.m16n8k8.row.col.f32.tf32.tf32.f32 "
        "{%0,%1,%2,%3}, {%4,%5,%6,%7}, {%8,%9}, {%0,%1,%2,%3};"
        : "+f"(c[0]), "+f"(c[1]), "+f"(c[2]), "+f"(c[3])
        : "r"(a[0]), "r"(a[1]), "r"(a[2]), "r"(a[3]), "r"(b0), "r"(b1));
}

// ---------------------------------------------------------------------------
// prep: zero accumulators, tf32 conversion, fp32 row norms
__global__ void prep_kernel(const float* __restrict__ lat,
                            const float* __restrict__ z) {
    int r = blockIdx.x * blockDim.x + threadIdx.x;
    if (r < 3) g_acc[r] = 0.0;
    if (r >= NROWS + MROWS) return;
    const float* src;
    uint32_t* dst;
    if (r < NROWS) {
        src = lat + (size_t)r * DDIM;
        dst = g_lat_t + (size_t)r * DDIM;
    } else {
        int rr = r - NROWS;
        src = z + (size_t)rr * DDIM;
        dst = g_z_t + (size_t)rr * DDIM;
    }
    float s = 0.f;
#pragma unroll
    for (int q = 0; q < DDIM; q++) {
        float x = src[q];
        uint32_t t;
        asm("cvt.rna.tf32.f32 %0, %1;" : "=r"(t) : "f"(x));
        dst[q] = t;
        s = fmaf(x, x, s);
    }
    g_norm[r] = s;
}

// ---------------------------------------------------------------------------
// pair kernel: each CTA handles one A tile (128 i-rows) x TWO consecutive
// 64-row j-tiles (A reused). 8 warps in 4(m) x 2(n); warp tile 32x32 via
// mma.m16n8k8.tf32: mt=2, nt=4, 8 k-steps.
// SELF: A==B; only strict-upper pairs (j > i) counted (doubled in finalize);
// blocks scheduled only where first j-tile pair index p >= bi.
template <bool SELF>
__global__ __launch_bounds__(256, 3)
void pair_kernel(int nAoff, int nBoff, int TP, int accIdx) {
    extern __shared__ uint32_t smf[];
    uint32_t* sA = smf;
    uint32_t* sB = smf + SM_B;
    float* nbS = (float*)(smf + SM_NB);
    float* naS = (float*)(smf + SM_NA);
    float* red = (float*)(smf + SM_RED);

    const int tid = threadIdx.x, wid = tid >> 5, lane = tid & 31;
    const int wm = wid >> 1, wn = wid & 1;

    int bi, p;
    if (SELF) {
        int b = blockIdx.x;
        bi = 0;
        while (b >= TP - bi) { b -= TP - bi; bi++; }
        p = bi + b;                       // j-tile-pair index, p >= bi
    } else {
        bi = blockIdx.x / TP;
        p = blockIdx.x - bi * TP;
    }
    const int i0 = bi * 128;

    const uint32_t *At, *Bt;
    if (accIdx == 0)      { At = g_lat_t; Bt = g_z_t;   }
    else if (accIdx == 1) { At = g_lat_t; Bt = g_lat_t; }
    else                  { At = g_z_t;   Bt = g_z_t;   }

    // ---- fill A tile (coalesced LDG.128 -> padded STS.128) + na ----
    {
        const uint4* Ag = (const uint4*)At + (size_t)i0 * 16;
#pragma unroll
        for (int it = 0; it < 8; it++) {
            int lin = tid + it * 256;          // 0..2047
            int row = lin >> 4, c = lin & 15;
            *(uint4*)(sA + row * 68 + c * 4) = Ag[lin];
        }
        if (tid < 128) naS[tid] = g_norm[nAoff + i0 + tid];
    }

    // fragment base offsets (words)
    const int aBase = (wm * 32 + (lane >> 2)) * 68 + (lane & 3);
    const int bBase = (wn * 32 + (lane >> 2)) * 68 + (lane & 3);

    float total = 0.f;

#pragma unroll
    for (int s = 0; s < 2; s++) {
        const int j0 = (2 * p + s) * 64;

        // ---- fill B tile + nb ----
        {
            const uint4* Bg = (const uint4*)Bt + (size_t)j0 * 16;
#pragma unroll
            for (int it = 0; it < 4; it++) {
                int lin = tid + it * 256;      // 0..1023
                int row = lin >> 4, c = lin & 15;
                *(uint4*)(sB + row * 68 + c * 4) = Bg[lin];
            }
            if (tid < 64) nbS[tid] = g_norm[nBoff + j0 + tid];
        }
        __syncthreads();

        // ---- 8 k-steps of m16n8k8 ----
        float acc[2][4][4];
#pragma unroll
        for (int mt = 0; mt < 2; mt++)
#pragma unroll
            for (int nt = 0; nt < 4; nt++)
#pragma unroll
                for (int e = 0; e < 4; e++) acc[mt][nt][e] = 0.f;

#pragma unroll
        for (int kb = 0; kb < 8; kb++) {
            uint32_t af[2][4];
#pragma unroll
            for (int mt = 0; mt < 2; mt++) {
                int o = aBase + mt * 16 * 68 + kb * 8;
                af[mt][0] = sA[o];
                af[mt][1] = sA[o + 8 * 68];
                af[mt][2] = sA[o + 4];
                af[mt][3] = sA[o + 8 * 68 + 4];
            }
            uint32_t bf[4][2];
#pragma unroll
            for (int nt = 0; nt < 4; nt++) {
                int o = bBase + nt * 8 * 68 + kb * 8;
                bf[nt][0] = sB[o];
                bf[nt][1] = sB[o + 4];
            }
#pragma unroll
            for (int mt = 0; mt < 2; mt++)
#pragma unroll
                for (int nt = 0; nt < 4; nt++)
                    mma_tf32(acc[mt][nt], af[mt], bf[nt][0], bf[nt][1]);
        }

        // ---- epilogue: dist = sqrt(max(na + nb - 2*dot, 0)), masked ----
        float na4[4];
        {
            int r0 = wm * 32 + (lane >> 2);
#pragma unroll
            for (int q = 0; q < 4; q++) na4[q] = naS[r0 + q * 8];
        }
        const int ib = i0 + wm * 32 + (lane >> 2);
        const int jb = j0 + wn * 32 + (lane & 3) * 2;

#pragma unroll
        for (int mt = 0; mt < 2; mt++) {
#pragma unroll
            for (int nt = 0; nt < 4; nt++) {
                float nb0 = nbS[wn * 32 + nt * 8 + (lane & 3) * 2];
                float nb1 = nbS[wn * 32 + nt * 8 + (lane & 3) * 2 + 1];
#pragma unroll
                for (int e = 0; e < 4; e++) {
                    float nb = (e & 1) ? nb1 : nb0;
                    float sq = fmaf(-2.f, acc[mt][nt][e],
                                    na4[mt * 2 + (e >> 1)] + nb);
                    float dist = sqrtf(fmaxf(sq, 0.f));
                    if (SELF) {
                        int ii = ib + mt * 16 + (e >> 1) * 8;
                        int jj = jb + nt * 8 + (e & 1);
                        if (jj <= ii) dist = 0.f;
                    }
                    total += dist;
                }
            }
        }
        __syncthreads();   // B/nb buffers reused next iteration
    }

    // ---- block reduce, one double atomic per CTA ----
#pragma unroll
    for (int off = 16; off; off >>= 1)
        total += __shfl_xor_sync(0xffffffffu, total, off);
    if (lane == 0) red[wid] = total;
    __syncthreads();
    if (tid == 0) {
        double t = 0.0;
#pragma unroll
        for (int w = 0; w < 8; w++) t += (double)red[w];
        atomicAdd(&g_acc[accIdx], t);
    }
}

// ---------------------------------------------------------------------------
__global__ void finalize_kernel(float* out) {
    double a1 = g_acc[0] * (2.0 / ((double)NROWS * MROWS * DDIM));
    double b1 = g_acc[1] * (2.0 / ((double)NROWS * NROWS * DDIM));  // 2x: upper only
    double c1 = g_acc[2] * (2.0 / ((double)MROWS * MROWS * DDIM));
    out[0] = (float)(a1 - b1 - c1);
}

// ---------------------------------------------------------------------------
extern "C" void kernel_launch(void* const* d_in, const int* in_sizes, int n_in,
                              void* d_out, int out_size) {
    const float* lat = (const float*)d_in[0];
    const float* z   = (const float*)d_in[1];
    if (n_in >= 2 && in_sizes[0] == MROWS * DDIM && in_sizes[1] == NROWS * DDIM) {
        const float* t = lat; lat = z; z = t;
    }
    float* out = (float*)d_out;

    // >48KB dynamic smem requires the attribute; idempotent, no allocation.
    cudaFuncSetAttribute(pair_kernel<false>,
                         cudaFuncAttributeMaxDynamicSharedMemorySize, SM_BYTES);
    cudaFuncSetAttribute(pair_kernel<true>,
                         cudaFuncAttributeMaxDynamicSharedMemorySize, SM_BYTES);

    prep_kernel<<<(NROWS + MROWS + 255) / 256, 256>>>(lat, z);

    // cross: 128 i-tiles x 32 j-tile-pairs
    pair_kernel<false><<<128 * 32, 256, SM_BYTES>>>(0, NROWS, 32, 0);
    // latent self: TP=128 pairs; blocks = sum_{bi=0}^{127}(128-bi) = 8256
    pair_kernel<true><<<8256, 256, SM_BYTES>>>(0, 0, 128, 1);
    // z self: TP=32; blocks = sum_{bi=0}^{31}(32-bi) = 528
    pair_kernel<true><<<528, 256, SM_BYTES>>>(NROWS, NROWS, 32, 2);

    finalize_kernel<<<1, 1>>>(out);
}

// round 6
// speedup vs baseline: 3.0455x; 1.0760x over previous
#include <cuda_runtime.h>
#include <cstdint>

// Energy-distance loss via single-pass tf32 register GEMM (mma.m16n8k8).
//   dist(i,j) = sqrt(max(|a_i|^2 + |b_j|^2 - 2 a_i.b_j, 0))
// tf32 inputs stored k-interleaved so fragment loads are LDS.64.
// Norms fp32; global sums in double, one atomic per CTA.

#define NROWS 16384
#define MROWS 4096
#define DDIM  64

__device__ double   g_acc[3];
__device__ float    g_norm[NROWS + MROWS];
__device__ uint32_t g_lat_t[NROWS * DDIM];   // tf32 bits, k-interleaved per row
__device__ uint32_t g_z_t[MROWS * DDIM];

// smem word layout: A 128x72, B[2] 64x72, na[128], nb[128], red[8]
static constexpr int STRIDE  = 72;
static constexpr int SM_B    = 128 * STRIDE;            // 9216
static constexpr int SM_NA   = SM_B + 2 * 64 * STRIDE;  // 18432
static constexpr int SM_NB   = SM_NA + 128;             // 18560
static constexpr int SM_RED  = SM_NB + 128;             // 18688
static constexpr int SM_WORDS = SM_RED + 8;             // 18696
static constexpr int SM_BYTES = SM_WORDS * 4;           // 74784

// ---------------------------------------------------------------------------
__device__ __forceinline__ uint32_t smem_u32(const void* p) {
    uint32_t a;
    asm("{ .reg .u64 t; cvta.to.shared.u64 t, %1; cvt.u32.u64 %0, t; }"
        : "=r"(a) : "l"(p));
    return a;
}
__device__ __forceinline__ void cp16(uint32_t saddr, const void* g) {
    asm volatile("cp.async.cg.shared.global [%0], [%1], 16;"
                 :: "r"(saddr), "l"(g));
}
__device__ __forceinline__ void mma_tf32(float* c, uint32_t a0, uint32_t a1,
                                         uint32_t a2, uint32_t a3,
                                         uint32_t b0, uint32_t b1) {
    asm volatile(
        "mma.sync.aligned.m16n8k8.row.col.f32.tf32.tf32.f32 "
        "{%0,%1,%2,%3}, {%4,%5,%6,%7}, {%8,%9}, {%0,%1,%2,%3};"
        : "+f"(c[0]), "+f"(c[1]), "+f"(c[2]), "+f"(c[3])
        : "r"(a0), "r"(a1), "r"(a2), "r"(a3), "r"(b0), "r"(b1));
}
__device__ __forceinline__ float sqrt_approx(float x) {
    float r;
    asm("sqrt.approx.f32 %0, %1;" : "=f"(r) : "f"(x));
    return r;
}

// ---------------------------------------------------------------------------
// prep: zero accumulators, tf32 convert + k-interleave, fp32 row norms.
// Interleave: logical col q (kb = q>>3, c = q&7) stored at
//   kb*8 + 2*(c&3) + (c>>2)  -> pairs (c, c+4) adjacent for LDS.64.
__global__ void prep_kernel(const float* __restrict__ lat,
                            const float* __restrict__ z) {
    int r = blockIdx.x * blockDim.x + threadIdx.x;
    if (r < 3) g_acc[r] = 0.0;
    if (r >= NROWS + MROWS) return;
    const float* src;
    uint32_t* dst;
    if (r < NROWS) {
        src = lat + (size_t)r * DDIM;
        dst = g_lat_t + (size_t)r * DDIM;
    } else {
        int rr = r - NROWS;
        src = z + (size_t)rr * DDIM;
        dst = g_z_t + (size_t)rr * DDIM;
    }
    float s = 0.f;
#pragma unroll
    for (int q = 0; q < DDIM; q++) {
        float x = src[q];
        uint32_t t;
        asm("cvt.rna.tf32.f32 %0, %1;" : "=r"(t) : "f"(x));
        int kb = q >> 3, c = q & 7;
        dst[kb * 8 + 2 * (c & 3) + (c >> 2)] = t;
        s = fmaf(x, x, s);
    }
    g_norm[r] = s;
}

// ---------------------------------------------------------------------------
// pair kernel: one CTA = A tile (128 i-rows) x two consecutive 64-row j-tiles,
// all tiles resident (one sync). 8 warps 4(m) x 2(n); warp tile 32x32.
// SELF: A==B; only strict-upper pairs (j > i) counted (doubled in finalize);
// blocks scheduled only where j-tile-pair index p >= bi.
template <bool SELF>
__global__ __launch_bounds__(256, 3)
void pair_kernel(int nAoff, int nBoff, int TP, int accIdx) {
    extern __shared__ uint32_t smf[];
    uint32_t* sA = smf;
    uint32_t* sB = smf + SM_B;
    float* naS = (float*)(smf + SM_NA);
    float* nbS = (float*)(smf + SM_NB);
    float* red = (float*)(smf + SM_RED);
    const uint32_t sbase = smem_u32(smf);

    const int tid = threadIdx.x, wid = tid >> 5, lane = tid & 31;
    const int wm = wid >> 1, wn = wid & 1;

    int bi, p;
    if (SELF) {
        int b = blockIdx.x;
        bi = 0;
        while (b >= TP - bi) { b -= TP - bi; bi++; }
        p = bi + b;
    } else {
        bi = blockIdx.x / TP;
        p = blockIdx.x - bi * TP;
    }
    const int i0 = bi * 128;
    const int j0 = p * 128;          // two consecutive 64-row tiles

    const uint32_t *At, *Bt;
    if (accIdx == 0)      { At = g_lat_t; Bt = g_z_t;   }
    else if (accIdx == 1) { At = g_lat_t; Bt = g_lat_t; }
    else                  { At = g_z_t;   Bt = g_z_t;   }

    // ---- async fill: A (2048 uint4) + both B tiles (2048 uint4) ----
    {
        const uint4* Ag = (const uint4*)At + (size_t)i0 * 16;
#pragma unroll
        for (int it = 0; it < 8; it++) {
            int lin = tid + it * 256;
            int row = lin >> 4, c = lin & 15;
            cp16(sbase + (uint32_t)(row * STRIDE + c * 4) * 4, Ag + lin);
        }
        const uint4* Bg = (const uint4*)Bt + (size_t)j0 * 16;
#pragma unroll
        for (int it = 0; it < 8; it++) {
            int lin = tid + it * 256;
            int jr = lin >> 4, c = lin & 15;     // jr 0..127
            int t = jr >> 6, rr = jr & 63;
            cp16(sbase + (uint32_t)(SM_B + t * 64 * STRIDE + rr * STRIDE + c * 4) * 4,
                 Bg + lin);
        }
        asm volatile("cp.async.commit_group;");
        if (tid < 128) naS[tid] = g_norm[nAoff + i0 + tid];
        if (tid >= 128) nbS[tid - 128] = g_norm[nBoff + j0 + tid - 128];
        asm volatile("cp.async.wait_group 0;" ::: "memory");
    }
    __syncthreads();

    // fragment word offsets
    const int aBase = (wm * 32 + (lane >> 2)) * STRIDE + 2 * (lane & 3);
    const int bBase0 = (wn * 32 + (lane >> 2)) * STRIDE + 2 * (lane & 3);

    float na4[4];
    {
        int r0 = wm * 32 + (lane >> 2);
#pragma unroll
        for (int q = 0; q < 4; q++) na4[q] = naS[r0 + q * 8];
    }
    const int ib = i0 + wm * 32 + (lane >> 2);

    float total = 0.f;

#pragma unroll
    for (int s = 0; s < 2; s++) {
        const uint32_t* sBt = sB + s * 64 * STRIDE;

        float acc[2][4][4];
#pragma unroll
        for (int mt = 0; mt < 2; mt++)
#pragma unroll
            for (int nt = 0; nt < 4; nt++)
#pragma unroll
                for (int e = 0; e < 4; e++) acc[mt][nt][e] = 0.f;

#pragma unroll
        for (int kb = 0; kb < 8; kb++) {
            const int ko = kb * 8;
            uint2 aLo[2], aHi[2];
#pragma unroll
            for (int mt = 0; mt < 2; mt++) {
                int o = aBase + mt * 16 * STRIDE + ko;
                aLo[mt] = *(const uint2*)(sA + o);                 // rows r
                aHi[mt] = *(const uint2*)(sA + o + 8 * STRIDE);    // rows r+8
            }
            uint2 bv[4];
#pragma unroll
            for (int nt = 0; nt < 4; nt++)
                bv[nt] = *(const uint2*)(sBt + bBase0 + nt * 8 * STRIDE + ko);
#pragma unroll
            for (int mt = 0; mt < 2; mt++)
#pragma unroll
                for (int nt = 0; nt < 4; nt++)
                    mma_tf32(acc[mt][nt],
                             aLo[mt].x, aHi[mt].x, aLo[mt].y, aHi[mt].y,
                             bv[nt].x, bv[nt].y);
        }

        // ---- epilogue ----
        const int jb = j0 + s * 64 + wn * 32 + (lane & 3) * 2;
#pragma unroll
        for (int mt = 0; mt < 2; mt++) {
#pragma unroll
            for (int nt = 0; nt < 4; nt++) {
                int nbi = s * 64 + wn * 32 + nt * 8 + (lane & 3) * 2;
                float nb0 = nbS[nbi], nb1 = nbS[nbi + 1];
#pragma unroll
                for (int e = 0; e < 4; e++) {
                    float nb = (e & 1) ? nb1 : nb0;
                    float sq = fmaf(-2.f, acc[mt][nt][e],
                                    na4[mt * 2 + (e >> 1)] + nb);
                    float dist = sqrt_approx(fmaxf(sq, 0.f));
                    if (SELF) {
                        int ii = ib + mt * 16 + (e >> 1) * 8;
                        int jj = jb + nt * 8 + (e & 1);
                        if (jj <= ii) dist = 0.f;
                    }
                    total += dist;
                }
            }
        }
    }

    // ---- block reduce, one double atomic per CTA ----
#pragma unroll
    for (int off = 16; off; off >>= 1)
        total += __shfl_xor_sync(0xffffffffu, total, off);
    if (lane == 0) red[wid] = total;
    __syncthreads();
    if (tid == 0) {
        double t = 0.0;
#pragma unroll
        for (int w = 0; w < 8; w++) t += (double)red[w];
        atomicAdd(&g_acc[accIdx], t);
    }
}

// ---------------------------------------------------------------------------
__global__ void finalize_kernel(float* out) {
    double a1 = g_acc[0] * (2.0 / ((double)NROWS * MROWS * DDIM));
    double b1 = g_acc[1] * (2.0 / ((double)NROWS * NROWS * DDIM));  // 2x: upper only
    double c1 = g_acc[2] * (2.0 / ((double)MROWS * MROWS * DDIM));
    out[0] = (float)(a1 - b1 - c1);
}

// ---------------------------------------------------------------------------
extern "C" void kernel_launch(void* const* d_in, const int* in_sizes, int n_in,
                              void* d_out, int out_size) {
    const float* lat = (const float*)d_in[0];
    const float* z   = (const float*)d_in[1];
    if (n_in >= 2 && in_sizes[0] == MROWS * DDIM && in_sizes[1] == NROWS * DDIM) {
        const float* t = lat; lat = z; z = t;
    }
    float* out = (float*)d_out;

    cudaFuncSetAttribute(pair_kernel<false>,
                         cudaFuncAttributeMaxDynamicSharedMemorySize, SM_BYTES);
    cudaFuncSetAttribute(pair_kernel<true>,
                         cudaFuncAttributeMaxDynamicSharedMemorySize, SM_BYTES);

    prep_kernel<<<(NROWS + MROWS + 255) / 256, 256>>>(lat, z);

    // cross: 128 i-tiles x 32 j-tile-pairs
    pair_kernel<false><<<128 * 32, 256, SM_BYTES>>>(0, NROWS, 32, 0);
    // latent self: TP=128 pairs -> 8256 blocks
    pair_kernel<true><<<8256, 256, SM_BYTES>>>(0, 0, 128, 1);
    // z self: TP=32 -> 528 blocks
    pair_kernel<true><<<528, 256, SM_BYTES>>>(NROWS, NROWS, 32, 2);

    finalize_kernel<<<1, 1>>>(out);
}

// round 7
// speedup vs baseline: 3.7985x; 1.2473x over previous
#include <cuda_runtime.h>
#include <cstdint>

// Energy-distance loss, tf32 mma.m16n8k8 with K-augmented norms:
//   A' = [-2a, na_hi, na_lo, 1, 1, pad0...]  (K = 72)
//   B' = [ b,   1,    1, nb_hi, nb_lo, pad0...]
//   acc = na + nb - 2 a.b  -> dist = sqrt.approx(acc)
// Epilogue is 2 ops/pair; diagonal-only masking (NaN at i==j -> select 0).
// Global sums in double, one atomic per CTA.

#define NROWS 16384
#define MROWS 4096
#define DDIM  64
#define KDIM  72      // 64 data + 5 norm/one slots + 3 zero pad (9 k-steps)

__device__ double   g_acc[3];
__device__ uint32_t g_latA[NROWS * KDIM];   // A-role (rows), k-interleaved
__device__ uint32_t g_latB[NROWS * KDIM];   // B-role (cols)
__device__ uint32_t g_zA[MROWS * KDIM];
__device__ uint32_t g_zB[MROWS * KDIM];

// smem words: A 128x72, B 128x72 (two 64-row j-tiles), red[8]
static constexpr int STRIDE  = KDIM;                 // 72 (== 8 mod 32: conflict-free)
static constexpr int SM_B    = 128 * STRIDE;         // 9216
static constexpr int SM_RED  = SM_B + 128 * STRIDE;  // 18432
static constexpr int SM_WORDS = SM_RED + 8;
static constexpr int SM_BYTES = SM_WORDS * 4;        // 73760

// grid split
static constexpr int G_CROSS = 128 * 32;             // 4096
static constexpr int G_LSELF = 8256;                 // sum_{bi<128}(128-bi)
static constexpr int G_ZSELF = 528;                  // sum_{bi<32}(32-bi)
static constexpr int G_ALL   = G_CROSS + G_LSELF + G_ZSELF;   // 12880

// ---------------------------------------------------------------------------
__device__ __forceinline__ uint32_t smem_u32(const void* p) {
    uint32_t a;
    asm("{ .reg .u64 t; cvta.to.shared.u64 t, %1; cvt.u32.u64 %0, t; }"
        : "=r"(a) : "l"(p));
    return a;
}
__device__ __forceinline__ void cp16(uint32_t saddr, const void* g) {
    asm volatile("cp.async.cg.shared.global [%0], [%1], 16;"
                 :: "r"(saddr), "l"(g));
}
__device__ __forceinline__ uint32_t to_tf32(float x) {
    uint32_t t;
    asm("cvt.rna.tf32.f32 %0, %1;" : "=r"(t) : "f"(x));
    return t;
}
__device__ __forceinline__ void mma_tf32(float* c, uint32_t a0, uint32_t a1,
                                         uint32_t a2, uint32_t a3,
                                         uint32_t b0, uint32_t b1) {
    asm volatile(
        "mma.sync.aligned.m16n8k8.row.col.f32.tf32.tf32.f32 "
        "{%0,%1,%2,%3}, {%4,%5,%6,%7}, {%8,%9}, {%0,%1,%2,%3};"
        : "+f"(c[0]), "+f"(c[1]), "+f"(c[2]), "+f"(c[3])
        : "r"(a0), "r"(a1), "r"(a2), "r"(a3), "r"(b0), "r"(b1));
}
__device__ __forceinline__ float sqrt_approx(float x) {
    float r;
    asm("sqrt.approx.f32 %0, %1;" : "=f"(r) : "f"(x));
    return r;
}

// k-interleave within each 8-col block: logical c -> 2*(c&3) + (c>>2)
__device__ __forceinline__ int ilv(int q) {
    return (q & ~7) + 2 * (q & 3) + ((q & 7) >> 2);
}

// ---------------------------------------------------------------------------
// prep: zero accumulators; build augmented, tf32, k-interleaved A/B role rows.
__global__ void prep_kernel(const float* __restrict__ lat,
                            const float* __restrict__ z) {
    int r = blockIdx.x * blockDim.x + threadIdx.x;
    if (r < 3) g_acc[r] = 0.0;
    if (r >= NROWS + MROWS) return;
    const float* src;
    uint32_t *dA, *dB;
    if (r < NROWS) {
        src = lat + (size_t)r * DDIM;
        dA = g_latA + (size_t)r * KDIM;
        dB = g_latB + (size_t)r * KDIM;
    } else {
        int rr = r - NROWS;
        src = z + (size_t)rr * DDIM;
        dA = g_zA + (size_t)rr * KDIM;
        dB = g_zB + (size_t)rr * KDIM;
    }
    float s = 0.f;
#pragma unroll
    for (int q = 0; q < DDIM; q++) {
        float x = src[q];
        int pos = ilv(q);
        dA[pos] = to_tf32(-2.f * x);
        dB[pos] = to_tf32(x);
        s = fmaf(x, x, s);
    }
    uint32_t nh = to_tf32(s);
    uint32_t nl = to_tf32(s - __uint_as_float(nh));
    const uint32_t one = 0x3f800000u;
    uint32_t av[8] = {nh, nl, one, one, 0, 0, 0, 0};
    uint32_t bv[8] = {one, one, nh, nl, 0, 0, 0, 0};
#pragma unroll
    for (int c = 0; c < 8; c++) {
        int pos = ilv(64 + c);
        dA[pos] = av[c];
        dB[pos] = bv[c];
    }
}

// ---------------------------------------------------------------------------
// fused pair kernel: block decodes its segment.
//   [0, 4096)        cross:   A=lat, B=z,  128 x 32 pair-tiles
//   [4096, 12352)    latent self (triangular, TP=128)
//   [12352, 12880)   z self (triangular, TP=32)
// Each CTA: A tile 128 rows x two consecutive 64-row j-tiles; 8 warps 4m x 2n.
__global__ __launch_bounds__(256, 3)
void pair_kernel() {
    extern __shared__ uint32_t smf[];
    uint32_t* sA = smf;
    uint32_t* sB = smf + SM_B;
    float* red = (float*)(smf + SM_RED);
    const uint32_t sbase = smem_u32(smf);

    const int tid = threadIdx.x, wid = tid >> 5, lane = tid & 31;
    const int wm = wid >> 1, wn = wid & 1;

    int bi, p, accIdx;
    bool self;
    const uint32_t *Abuf, *Bbuf;
    {
        int bid = blockIdx.x;
        if (bid < G_CROSS) {
            bi = bid >> 5; p = bid & 31;
            Abuf = g_latA; Bbuf = g_zB; accIdx = 0; self = false;
        } else if (bid < G_CROSS + G_LSELF) {
            int b = bid - G_CROSS;
            bi = 0;
            while (b >= 128 - bi) { b -= 128 - bi; bi++; }
            p = bi + b;
            Abuf = g_latA; Bbuf = g_latB; accIdx = 1; self = true;
        } else {
            int b = bid - (G_CROSS + G_LSELF);
            bi = 0;
            while (b >= 32 - bi) { b -= 32 - bi; bi++; }
            p = bi + b;
            Abuf = g_zA; Bbuf = g_zB; accIdx = 2; self = true;
        }
    }
    const int i0 = bi * 128;
    const int j0 = p * 128;
    const bool diag = self && (p == bi);

    // ---- async fill: A rows i0..+128, B rows j0..+128 (18 uint4/row) ----
    {
        const char* Ag = (const char*)(Abuf + (size_t)i0 * KDIM);
        const char* Bg = (const char*)(Bbuf + (size_t)j0 * KDIM);
#pragma unroll
        for (int it = 0; it < 9; it++) {
            int lin = tid + it * 256;            // 0..2303
            int row = lin / 18, c = lin % 18;
            uint32_t off = (uint32_t)(row * STRIDE + c * 4) * 4;
            cp16(sbase + off, Ag + (size_t)row * KDIM * 4 + c * 16);
            cp16(sbase + SM_B * 4 + off, Bg + (size_t)row * KDIM * 4 + c * 16);
        }
        asm volatile("cp.async.commit_group;");
        asm volatile("cp.async.wait_group 0;" ::: "memory");
    }
    __syncthreads();

    const int aBase = (wm * 32 + (lane >> 2)) * STRIDE + 2 * (lane & 3);
    const int bBase = (wn * 32 + (lane >> 2)) * STRIDE + 2 * (lane & 3);
    const int ib = i0 + wm * 32 + (lane >> 2);

    float tot0 = 0.f, tot1 = 0.f;

#pragma unroll
    for (int s = 0; s < 2; s++) {
        const uint32_t* sBt = sB + s * 64 * STRIDE;

        float acc[2][4][4];
#pragma unroll
        for (int mt = 0; mt < 2; mt++)
#pragma unroll
            for (int nt = 0; nt < 4; nt++)
#pragma unroll
                for (int e = 0; e < 4; e++) acc[mt][nt][e] = 0.f;

#pragma unroll
        for (int kb = 0; kb < 9; kb++) {
            const int ko = kb * 8;
            uint2 aLo[2], aHi[2];
#pragma unroll
            for (int mt = 0; mt < 2; mt++) {
                int o = aBase + mt * 16 * STRIDE + ko;
                aLo[mt] = *(const uint2*)(sA + o);
                aHi[mt] = *(const uint2*)(sA + o + 8 * STRIDE);
            }
            uint2 bv[4];
#pragma unroll
            for (int nt = 0; nt < 4; nt++)
                bv[nt] = *(const uint2*)(sBt + bBase + nt * 8 * STRIDE + ko);
#pragma unroll
            for (int mt = 0; mt < 2; mt++)
#pragma unroll
                for (int nt = 0; nt < 4; nt++)
                    mma_tf32(acc[mt][nt],
                             aLo[mt].x, aHi[mt].x, aLo[mt].y, aHi[mt].y,
                             bv[nt].x, bv[nt].y);
        }

        // ---- epilogue: acc IS sq; sqrt + accumulate ----
        if (!diag) {
#pragma unroll
            for (int mt = 0; mt < 2; mt++)
#pragma unroll
                for (int nt = 0; nt < 4; nt++) {
#pragma unroll
                    for (int e = 0; e < 4; e += 2) {
                        tot0 += sqrt_approx(acc[mt][nt][e]);
                        tot1 += sqrt_approx(acc[mt][nt][e + 1]);
                    }
                }
        } else {
            const int jb = j0 + s * 64 + wn * 32 + (lane & 3) * 2;
#pragma unroll
            for (int mt = 0; mt < 2; mt++)
#pragma unroll
                for (int nt = 0; nt < 4; nt++)
#pragma unroll
                    for (int e = 0; e < 4; e++) {
                        float dist = sqrt_approx(acc[mt][nt][e]);
                        int ii = ib + mt * 16 + (e >> 1) * 8;
                        int jj = jb + nt * 8 + (e & 1);
                        if (jj <= ii) dist = 0.f;   // also kills i==j NaN
                        if (e & 1) tot1 += dist; else tot0 += dist;
                    }
        }
    }

    // ---- block reduce, one double atomic per CTA ----
    float total = tot0 + tot1;
#pragma unroll
    for (int off = 16; off; off >>= 1)
        total += __shfl_xor_sync(0xffffffffu, total, off);
    if (lane == 0) red[wid] = total;
    __syncthreads();
    if (tid == 0) {
        double t = 0.0;
#pragma unroll
        for (int w = 0; w < 8; w++) t += (double)red[w];
        atomicAdd(&g_acc[accIdx], t);
    }
}

// ---------------------------------------------------------------------------
__global__ void finalize_kernel(float* out) {
    double a1 = g_acc[0] * (2.0 / ((double)NROWS * MROWS * DDIM));
    double b1 = g_acc[1] * (2.0 / ((double)NROWS * NROWS * DDIM));  // 2x: upper only
    double c1 = g_acc[2] * (2.0 / ((double)MROWS * MROWS * DDIM));
    out[0] = (float)(a1 - b1 - c1);
}

// ---------------------------------------------------------------------------
extern "C" void kernel_launch(void* const* d_in, const int* in_sizes, int n_in,
                              void* d_out, int out_size) {
    const float* lat = (const float*)d_in[0];
    const float* z   = (const float*)d_in[1];
    if (n_in >= 2 && in_sizes[0] == MROWS * DDIM && in_sizes[1] == NROWS * DDIM) {
        const float* t = lat; lat = z; z = t;
    }
    float* out = (float*)d_out;

    cudaFuncSetAttribute(pair_kernel,
                         cudaFuncAttributeMaxDynamicSharedMemorySize, SM_BYTES);

    prep_kernel<<<(NROWS + MROWS + 255) / 256, 256>>>(lat, z);
    pair_kernel<<<G_ALL, 256, SM_BYTES>>>();
    finalize_kernel<<<1, 1>>>(out);
}